// round 15
// baseline (speedup 1.0000x reference)
#include <cuda_runtime.h>
#include <cuda_bf16.h>
#include <cstdint>
#include <cstddef>

#define VOCABN 50257
#define EMBN   256
#define HIDN   256
#define NBATCH 64
#define SEQT   2048
#define G3     768

// 154 MB scratch: E'[v][j] = emb[v] . W_ih[j] + b_ih[j]
__device__ float g_Ep[(size_t)VOCABN * G3];

// ---------------------------------------------------------------------------
// helpers
// ---------------------------------------------------------------------------
__device__ __forceinline__ float bflo(unsigned u) { return __uint_as_float(u << 16); }
__device__ __forceinline__ float bfhi(unsigned u) { return __uint_as_float(u & 0xffff0000u); }
__device__ __forceinline__ float tanhapx(float x) {
    float y;
    asm("tanh.approx.f32 %0, %1;" : "=f"(y) : "f"(x));
    return y;
}
__device__ __forceinline__ float sigapx(float x) {   // 0.5 + 0.5*tanh(x/2)
    return fmaf(0.5f, tanhapx(0.5f * x), 0.5f);
}
__device__ __forceinline__ unsigned smem_u32(const void* p) {
    unsigned a;
    asm("{ .reg .u64 t; cvta.to.shared.u64 t, %1; cvt.u32.u64 %0, t; }" : "=r"(a) : "l"(p));
    return a;
}
__device__ __forceinline__ unsigned bffma2(unsigned a, unsigned b, unsigned c) {
    unsigned d;
    asm("fma.rn.bf16x2 %0, %1, %2, %3;" : "=r"(d) : "r"(a), "r"(b), "r"(c));
    return d;
}
__device__ __forceinline__ unsigned pack_bf2(float lo, float hi) {
    __nv_bfloat162 p = __floats2bfloat162_rn(lo, hi);
    return *(unsigned*)&p;
}
__device__ __forceinline__ void mbar_wait(unsigned mbar, unsigned parity) {
    asm volatile(
        "{\n\t.reg .pred P;\n\t"
        "WL_%=:\n\t"
        "mbarrier.try_wait.parity.acquire.cta.shared::cta.b64 P, [%0], %1, 0x989680;\n\t"
        "@P bra.uni WD_%=;\n\t"
        "bra.uni WL_%=;\n\t"
        "WD_%=:\n\t}"
        :: "r"(mbar), "r"(parity) : "memory");
}
__device__ __forceinline__ void mma16816(float* c,
    unsigned a0, unsigned a1, unsigned a2, unsigned a3,
    unsigned b0, unsigned b1)
{
    asm("mma.sync.aligned.m16n8k16.row.col.f32.bf16.bf16.f32 "
        "{%0,%1,%2,%3}, {%4,%5,%6,%7}, {%8,%9}, {%0,%1,%2,%3};"
        : "+f"(c[0]), "+f"(c[1]), "+f"(c[2]), "+f"(c[3])
        : "r"(a0), "r"(a1), "r"(a2), "r"(a3), "r"(b0), "r"(b1));
}

// ---------------------------------------------------------------------------
// Phase A: E' = emb @ W_ih^T + b_ih via bf16 mma.sync (unchanged from R11).
// ---------------------------------------------------------------------------
#define AW 132
#define EPR_SMEM ((128 + 64) * AW * 4)   // 101376 B

__global__ void __launch_bounds__(256) eprime_tc_kernel(
    const float* __restrict__ emb, const float* __restrict__ W_ih,
    const float* __restrict__ b_ih)
{
    extern __shared__ unsigned ts[];
    unsigned* sA = ts;                 // 128 x 132 words
    unsigned* sB = ts + 128 * AW;      // 64 x 132 words

    const int tid  = threadIdx.x;
    const int m0   = blockIdx.x * 128;
    const int warp = tid >> 5;
    const int lane = tid & 31;
    const int g    = lane >> 2;
    const int t    = lane & 3;
    const int mrow = warp * 16;

    for (int i = tid; i < 128 * 128; i += 256) {
        int r = i >> 7, w = i & 127;
        int gm = m0 + r; if (gm >= VOCABN) gm = VOCABN - 1;
        float2 f = *(const float2*)&emb[(size_t)gm * EMBN + w * 2];
        sA[r * AW + w] = pack_bf2(f.x, f.y);
    }

    for (int nb = 0; nb < 12; nb++) {
        __syncthreads();
        for (int i = tid; i < 64 * 128; i += 256) {
            int r = i >> 7, w = i & 127;
            float2 f = *(const float2*)&W_ih[(size_t)(nb * 64 + r) * EMBN + w * 2];
            sB[r * AW + w] = pack_bf2(f.x, f.y);
        }
        __syncthreads();

        float acc[8][4];
#pragma unroll
        for (int nf = 0; nf < 8; nf++)
#pragma unroll
            for (int j = 0; j < 4; j++) acc[nf][j] = 0.f;

#pragma unroll 4
        for (int ks = 0; ks < 16; ks++) {
            const int kw = ks * 8;
            unsigned a0 = sA[(mrow + g)     * AW + kw + t];
            unsigned a1 = sA[(mrow + g + 8) * AW + kw + t];
            unsigned a2 = sA[(mrow + g)     * AW + kw + 4 + t];
            unsigned a3 = sA[(mrow + g + 8) * AW + kw + 4 + t];
#pragma unroll
            for (int nf = 0; nf < 8; nf++) {
                unsigned b0 = sB[(nf * 8 + g) * AW + kw + t];
                unsigned b1 = sB[(nf * 8 + g) * AW + kw + 4 + t];
                mma16816(acc[nf], a0, a1, a2, a3, b0, b1);
            }
        }

#pragma unroll
        for (int nf = 0; nf < 8; nf++) {
            int n  = nb * 64 + nf * 8 + 2 * t;
            float bi0 = b_ih[n], bi1 = b_ih[n + 1];
            int r0 = m0 + mrow + g;
            int r1 = r0 + 8;
            if (r0 < VOCABN) {
                float2 v; v.x = acc[nf][0] + bi0; v.y = acc[nf][1] + bi1;
                *(float2*)&g_Ep[(size_t)r0 * G3 + n] = v;
            }
            if (r1 < VOCABN) {
                float2 v; v.x = acc[nf][2] + bi0; v.y = acc[nf][3] + bi1;
                *(float2*)&g_Ep[(size_t)r1 * G3 + n] = v;
            }
        }
    }
}

// ---------------------------------------------------------------------------
// Phase B: scan. Cluster of 2 CTAs per batch element, 256 FAT threads/CTA.
// Thread = (unit jj = tid>>1, split s = tid&1): 192 weight uints in regs.
// Sync protocol (R15):
//  - local h coherence: __syncthreads
//  - peer exchange: s==1 threads (who computed the same hn redundantly) push
//    their unit's h DIRECTLY to the peer (st.shared::cluster.u16) right after
//    the epilogue, each followed by its own arrive.release.cluster on peer's
//    mbarP (count 128). No post-BAR push stage at all.
//  Ordering: each arrive is post-shfl_xor_sync (orders that warp's segB
//  reads); waitP needs arrivals from s1 threads of ALL 8 warps, so waitP(t)
//  passing implies all peer reads of step t-1 finished AND peer h(t) stores
//  are visible (release->acquire). Local anti-deps covered by the BAR.
// ---------------------------------------------------------------------------
// smem layout (bytes):
//   [0,    1152)  h_bf   2 buffers x 4 blocks x 144 B (64 bf16 + 16 pad)
//   [1152, 9344)  tok_s  2048 int32
//   [9344, 9352)  mbarP
#define SCAN_SMEM 9352
#define HBUF_STRIDE 576   // bytes per h buffer (4 blocks x 144)

__global__ void __cluster_dims__(2, 1, 1) __launch_bounds__(256, 1) scan_kernel(
    const int* __restrict__ tokens, const float* __restrict__ W_hh,
    const float* __restrict__ b_hh, const float* __restrict__ W_fc,
    const float* __restrict__ b_fc, float* __restrict__ out)
{
    extern __shared__ char smem[];
    char* h_raw = smem;
    int*  tok_s = (int*)(smem + 1152);
    const unsigned mbarP = smem_u32(smem + 9344);

    const int tid = threadIdx.x;
    const int b   = blockIdx.x >> 1;
    unsigned rank;
    asm("mov.u32 %0, %%cluster_ctarank;" : "=r"(rank));
    const unsigned peer = rank ^ 1u;
    const int jj = tid >> 1;              // local hidden unit 0..127
    const int s  = tid & 1;               // column split within each half
    const int gj = (int)rank * 128 + jj;  // global hidden unit

    // ---- init: ALL weights in registers (6 x 32 uints) ----
    unsigned aR[32], aZ[32], aN[32];      // local segment
    unsigned bR[32], bZ[32], bN[32];      // peer segment
    {
        const float2* pr = (const float2*)(W_hh + (size_t)(gj)       * HIDN);
        const float2* pz = (const float2*)(W_hh + (size_t)(256 + gj) * HIDN);
        const float2* pn = (const float2*)(W_hh + (size_t)(512 + gj) * HIDN);
        const int la = (int)rank * 64 + s * 32;   // local float2 base
        const int pa = (int)peer * 64 + s * 32;   // peer float2 base
#pragma unroll
        for (int i = 0; i < 32; i++) {
            float2 f;
            f = pr[la + i]; aR[i] = pack_bf2(f.x, f.y);
            f = pr[pa + i]; bR[i] = pack_bf2(f.x, f.y);
            f = pz[la + i]; aZ[i] = pack_bf2(f.x, f.y);
            f = pz[pa + i]; bZ[i] = pack_bf2(f.x, f.y);
            f = pn[la + i]; aN[i] = pack_bf2(f.x, f.y);
            f = pn[pa + i]; bN[i] = pack_bf2(f.x, f.y);
        }
    }
    const float bhr = b_hh[gj];
    const float bhz = b_hh[256 + gj];
    const float bhn2 = 0.5f * b_hh[512 + gj];

    for (int i = tid; i < SEQT; i += 256) tok_s[i] = tokens[b * SEQT + i];
    for (int i = tid; i < 2 * HBUF_STRIDE / 4; i += 256) ((unsigned*)h_raw)[i] = 0u;
    if (tid == 0) {
        asm volatile("mbarrier.init.shared.b64 [%0], %1;" :: "r"(mbarP), "r"(128u) : "memory");
    }
    __syncthreads();
    asm volatile("barrier.cluster.arrive.aligned;" ::: "memory");
    asm volatile("barrier.cluster.wait.aligned;"  ::: "memory");

    // prime phase 0 of peer's mbarP (h(0) already zeroed on both sides)
    if (s == 1) {
        asm volatile(
            "{ .reg .u32 ra; mapa.shared::cluster.u32 ra, %0, %1;"
            "  mbarrier.arrive.release.cluster.shared::cluster.b64 _, [ra]; }"
            :: "r"(mbarP), "r"(peer) : "memory");
    }

    const int blkA = (int)rank * 2 + s;           // local-segment h block
    const int blkB = (int)peer * 2 + s;           // peer-segment h block
    const int hoff = (gj >> 6) * 144 + (gj & 63) * 2;  // this unit's h slot
    float hreg = 0.f;

    const float* ep0 = &g_Ep[(size_t)tok_s[0] * G3];
    float gir = __ldg(ep0 + gj)       + bhr;
    float giz = __ldg(ep0 + 256 + gj) + bhz;
    float gin = __ldg(ep0 + 512 + gj);

    for (int t = 0; t < SEQT; t++) {
        const int cur = t & 1;
        const int nxt = cur ^ 1;
        const unsigned par = (unsigned)(t & 1);

        // prefetch next step's preactivations (independent of h)
        const int tn = (t + 1 < SEQT) ? tok_s[t + 1] : tok_s[t];
        const float* epn = &g_Ep[(size_t)tn * G3];
        float girn = __ldg(epn + gj);
        float gizn = __ldg(epn + 256 + gj);
        float ginn = __ldg(epn + 512 + gj);

        unsigned ar0 = 0u, ar1 = 0u, az0 = 0u, az1 = 0u, an0 = 0u, an1 = 0u;

        // ---- segment A: local 64 cols (gated by previous step's BAR) ----
        {
            const uint4* hA = (const uint4*)(h_raw + cur * HBUF_STRIDE + blkA * 144);
#pragma unroll
            for (int k = 0; k < 8; k++) {
                uint4 h = hA[k];
                ar0 = bffma2(aR[4 * k + 0], h.x, ar0);
                ar1 = bffma2(aR[4 * k + 1], h.y, ar1);
                az0 = bffma2(aZ[4 * k + 0], h.x, az0);
                az1 = bffma2(aZ[4 * k + 1], h.y, az1);
                an0 = bffma2(aN[4 * k + 0], h.x, an0);
                an1 = bffma2(aN[4 * k + 1], h.y, an1);
                ar0 = bffma2(aR[4 * k + 2], h.z, ar0);
                ar1 = bffma2(aR[4 * k + 3], h.w, ar1);
                az0 = bffma2(aZ[4 * k + 2], h.z, az0);
                az1 = bffma2(aZ[4 * k + 3], h.w, az1);
                an0 = bffma2(aN[4 * k + 2], h.z, an0);
                an1 = bffma2(aN[4 * k + 3], h.w, an1);
            }
        }

        // ---- segment B: peer 64 cols (gated by peer s1 pushes) ----
        mbar_wait(mbarP, par);
        {
            const uint4* hB = (const uint4*)(h_raw + cur * HBUF_STRIDE + blkB * 144);
#pragma unroll
            for (int k = 0; k < 8; k++) {
                uint4 h = hB[k];
                ar0 = bffma2(bR[4 * k + 0], h.x, ar0);
                ar1 = bffma2(bR[4 * k + 1], h.y, ar1);
                az0 = bffma2(bZ[4 * k + 0], h.x, az0);
                az1 = bffma2(bZ[4 * k + 1], h.y, az1);
                an0 = bffma2(bN[4 * k + 0], h.x, an0);
                an1 = bffma2(bN[4 * k + 1], h.y, an1);
                ar0 = bffma2(bR[4 * k + 2], h.z, ar0);
                ar1 = bffma2(bR[4 * k + 3], h.w, ar1);
                az0 = bffma2(bZ[4 * k + 2], h.z, az0);
                az1 = bffma2(bZ[4 * k + 3], h.w, az1);
                an0 = bffma2(bN[4 * k + 2], h.z, an0);
                an1 = bffma2(bN[4 * k + 3], h.w, an1);
            }
        }

        float sr = (bflo(ar0) + bfhi(ar0)) + (bflo(ar1) + bfhi(ar1));
        float sz = (bflo(az0) + bfhi(az0)) + (bflo(az1) + bfhi(az1));
        float sn = (bflo(an0) + bfhi(an0)) + (bflo(an1) + bfhi(an1)) + bhn2;

        // 2-way reduce across the s pair (full-warp sync: orders segB reads)
        sr += __shfl_xor_sync(0xffffffffu, sr, 1);
        sz += __shfl_xor_sync(0xffffffffu, sz, 1);
        sn += __shfl_xor_sync(0xffffffffu, sn, 1);

        // ---- epilogue (both s threads redundantly) ----
        float r  = sigapx(gir + sr);
        float z  = sigapx(giz + sz);
        float n  = tanhapx(fmaf(r, sn, gin));
        float hn = fmaf(z, hreg - n, n);        // (1-z)*n + z*h
        hreg = hn;

        {
            __nv_bfloat16 hb = __float2bfloat16(hn);
            if (s == 0) {
                // local store; ordered for local readers by the BAR below
                *(__nv_bfloat16*)(h_raw + nxt * HBUF_STRIDE + hoff) = hb;
            } else {
                // direct remote push + own release-arrive (orders own store)
                unsigned short hb16 = *(unsigned short*)&hb;
                unsigned dst = smem_u32(h_raw + nxt * HBUF_STRIDE + hoff);
                asm volatile(
                    "{ .reg .u32 ra; mapa.shared::cluster.u32 ra, %0, %1;"
                    "  st.shared::cluster.u16 [ra], %2; }"
                    :: "r"(dst), "r"(peer), "h"(hb16) : "memory");
                asm volatile(
                    "{ .reg .u32 ra; mapa.shared::cluster.u32 ra, %0, %1;"
                    "  mbarrier.arrive.release.cluster.shared::cluster.b64 _, [ra]; }"
                    :: "r"(mbarP), "r"(peer) : "memory");
            }
        }
        __syncthreads();   // orders local h stores; gates next segA

        gir = girn + bhr;
        giz = gizn + bhz;
        gin = ginn;
    }

    // wait for the final pushes (step 2047's arrivals complete phase 2048)
    mbar_wait(mbarP, 0u);

    // ---- final FC + sigmoid: final h lives in buffer 0 (2048 even) ----
    if (rank == 0 && tid < 64) {
        const int o = tid >> 5;
        const int lane = tid & 31;
        float sacc = 0.f;
#pragma unroll
        for (int i = 0; i < 8; i++) {
            int k = lane * 8 + i;
            const __nv_bfloat16* hp =
                (const __nv_bfloat16*)(h_raw + (k >> 6) * 144 + (k & 63) * 2);
            sacc = fmaf(__bfloat162float(*hp), W_fc[o * HIDN + k], sacc);
        }
#pragma unroll
        for (int off = 16; off; off >>= 1)
            sacc += __shfl_xor_sync(0xffffffffu, sacc, off);
        if (lane == 0) out[b * 2 + o] = __fdividef(1.f, 1.f + __expf(-(sacc + b_fc[o])));
    }
}

// ---------------------------------------------------------------------------
// launch
// ---------------------------------------------------------------------------
extern "C" void kernel_launch(void* const* d_in, const int* in_sizes, int n_in,
                              void* d_out, int out_size)
{
    const int*   tokens = (const int*)  d_in[0];
    const float* emb    = (const float*)d_in[1];
    const float* W_ih   = (const float*)d_in[2];
    const float* W_hh   = (const float*)d_in[3];
    const float* b_ih   = (const float*)d_in[4];
    const float* b_hh   = (const float*)d_in[5];
    const float* W_fc   = (const float*)d_in[6];
    const float* b_fc   = (const float*)d_in[7];
    float* out = (float*)d_out;

    cudaFuncSetAttribute(eprime_tc_kernel,
                         cudaFuncAttributeMaxDynamicSharedMemorySize, EPR_SMEM);
    cudaFuncSetAttribute(scan_kernel,
                         cudaFuncAttributeMaxDynamicSharedMemorySize, SCAN_SMEM);

    eprime_tc_kernel<<<(VOCABN + 127) / 128, 256, EPR_SMEM>>>(emb, W_ih, b_ih);

    scan_kernel<<<2 * NBATCH, 256, SCAN_SMEM>>>(tokens, W_hh, b_hh, W_fc, b_fc, out);

    (void)in_sizes; (void)n_in; (void)out_size;
}